// round 16
// baseline (speedup 1.0000x reference)
#include <cuda_runtime.h>
#include <cuda_bf16.h>

#define QSCALE 0.17677669529663687f   // 32^-0.5

typedef unsigned long long u64;
typedef unsigned int u32;

// ---------------------------------------------------------------------------
// Scratch (static device arrays; no allocation allowed)
// ---------------------------------------------------------------------------
__device__ __align__(16) float g_q  [32 * 1024 * 32];     // [bh][pos][d] (scaled)
__device__ __align__(16) float g_k  [32 * 1024 * 32];
__device__ __align__(16) float g_v  [32 * 1024 * 32];
__device__ __align__(16) float g_rx [32 * 1024 * 32];     // [bh][i][jc]
__device__ __align__(16) float g_ry [32 * 1024 * 32];     // [bh][i][jr]
__device__ __align__(16) float g_att[4 * 256 * 1024];     // scrambled-channel att
__device__ __align__(16) uint4  g_kbf[32 * 128 * 2 * 32]; // split-bf16 K B-frags
__device__ __align__(16) float2 g_vf[32 * 128 * 4 * 32];  // tf32 V frags (row-permuted)
__device__ __align__(16) uint4 g_xf_hi[256 * 72 * 32];    // im2col A frags (bf16 hi)
__device__ __align__(16) uint4 g_xf_lo[256 * 72 * 32];    // im2col A frags (bf16 lo)
__device__ __align__(16) uint4 g_wf   [72 * 128 * 32];    // conv weight B frags
__device__ __align__(16) uint4 g_pf   [16 * 32 * 32];     // proj weight B frags

// ---------------------------------------------------------------------------
// bf16 helpers
// ---------------------------------------------------------------------------
__device__ __forceinline__ u32 bpack(__nv_bfloat16 a, __nv_bfloat16 b) {
    return (u32)__bfloat16_as_ushort(a) | ((u32)__bfloat16_as_ushort(b) << 16);
}
__device__ __forceinline__ void bsplit2(float v0, float v1, u32& hi, u32& lo) {
    __nv_bfloat16 h0 = __float2bfloat16_rn(v0), h1 = __float2bfloat16_rn(v1);
    __nv_bfloat16 l0 = __float2bfloat16_rn(v0 - __bfloat162float(h0));
    __nv_bfloat16 l1 = __float2bfloat16_rn(v1 - __bfloat162float(h1));
    hi = bpack(h0, h1); lo = bpack(l0, l1);
}
#define MMA_BF16(d0,d1,d2,d3,a0,a1,a2,a3,b0,b1)                                \
    asm("mma.sync.aligned.m16n8k16.row.col.f32.bf16.bf16.f32 "                  \
        "{%0,%1,%2,%3},{%4,%5,%6,%7},{%8,%9},{%0,%1,%2,%3};"                    \
        : "+f"(d0), "+f"(d1), "+f"(d2), "+f"(d3)                                \
        : "r"(a0), "r"(a1), "r"(a2), "r"(a3), "r"(b0), "r"(b1))

__device__ __forceinline__ void cp16(u32 saddr, const void* g) {
    asm volatile("cp.async.cg.shared.global [%0], [%1], 16;" :: "r"(saddr), "l"(g));
}
#define CP_COMMIT() asm volatile("cp.async.commit_group;")
#define CP_WAIT0()  asm volatile("cp.async.wait_group 0;")
#define CP_WAIT1()  asm volatile("cp.async.wait_group 1;")

// ---------------------------------------------------------------------------
// tf32 helpers
// ---------------------------------------------------------------------------
__device__ __forceinline__ u32 tf32_of(float f) {
    u32 r; asm("cvt.rna.tf32.f32 %0,%1;" : "=r"(r) : "f"(f)); return r;
}
#define MMA_TF32(d0,d1,d2,d3,a0,a1,a2,a3,b0,b1)                                \
    asm("mma.sync.aligned.m16n8k8.row.col.f32.tf32.tf32.f32 "                   \
        "{%0,%1,%2,%3},{%4,%5,%6,%7},{%8,%9},{%0,%1,%2,%3};"                    \
        : "+f"(d0), "+f"(d1), "+f"(d2), "+f"(d3)                                \
        : "r"(a0), "r"(a1), "r"(a2), "r"(a3), "r"(b0), "r"(b1))

// ---------------------------------------------------------------------------
// K_xf: im2col -> split-bf16 A fragments in MMA lane order.
// ---------------------------------------------------------------------------
__global__ __launch_bounds__(256) void k_xf(const float* __restrict__ x) {
    __shared__ float Xs[128][3][20];
    const int pt = blockIdx.x, tid = threadIdx.x;
    const int pos0 = pt * 16;
    const int b = pos0 >> 10, y = (pos0 >> 5) & 31, x0 = pos0 & 31;

    for (int t = tid; t < 128 * 54; t += 256) {
        int ci = t / 54, rem = t - ci * 54;
        int ky = rem / 18, cc = rem - ky * 18;
        int gy = y + ky - 1, gx = x0 - 1 + cc;
        float v = 0.f;
        if ((unsigned)gy < 32u && (unsigned)gx < 32u)
            v = x[(size_t)((b * 128 + ci) * 32 + gy) * 32 + gx];
        Xs[ci][ky][cc] = v;
    }
    __syncthreads();

    for (int u = tid; u < 72 * 32; u += 256) {
        int ks = u >> 5, lane = u & 31;
        int gid = lane >> 2, tig = lane & 3;
        int r0 = gid, r1 = gid + 8;
        u32 hi[4], lo[4];
#pragma unroll
        for (int half = 0; half < 2; half++) {
            int k0 = ks * 16 + 2 * tig + half * 8;
            int k1 = k0 + 1;
            int ci0 = k0 / 9, tp0 = k0 - ci0 * 9;
            int ci1 = k1 / 9, tp1 = k1 - ci1 * 9;
            int ky0 = tp0 / 3, kx0 = tp0 - ky0 * 3;
            int ky1 = tp1 / 3, kx1 = tp1 - ky1 * 3;
            float A00 = Xs[ci0][ky0][r0 + kx0];
            float A01 = Xs[ci1][ky1][r0 + kx1];
            float A10 = Xs[ci0][ky0][r1 + kx0];
            float A11 = Xs[ci1][ky1][r1 + kx1];
            bsplit2(A00, A01, hi[half * 2],     lo[half * 2]);
            bsplit2(A10, A11, hi[half * 2 + 1], lo[half * 2 + 1]);
        }
        size_t idx = ((size_t)pt * 72 + ks) * 32 + lane;
        g_xf_hi[idx] = make_uint4(hi[0], hi[1], hi[2], hi[3]);
        g_xf_lo[idx] = make_uint4(lo[0], lo[1], lo[2], lo[3]);
    }
}

// ---------------------------------------------------------------------------
// K_wf: conv weights -> split-bf16 B fragments.
// ---------------------------------------------------------------------------
__global__ __launch_bounds__(256) void k_wf(const float* __restrict__ cw,
                                            const float* __restrict__ qw) {
    __shared__ float W[16][132];
    const int ct = blockIdx.x, ks0 = blockIdx.y * 9, tid = threadIdx.x;
    for (int ks = ks0; ks < ks0 + 9; ks++) {
        __syncthreads();
        for (int t = tid; t < 2048; t += 256) {
            int kl = t & 15, col = t >> 4;
            int co = ct * 128 + col;
            const float* src = (co < 256) ? cw + (size_t)co * 1152
                                          : qw + (size_t)(co - 256) * 1152;
            W[kl][col] = src[ks * 16 + kl];
        }
        __syncthreads();
        for (int u = tid; u < 512; u += 256) {
            int ntl = u >> 5, lane = u & 31, gid = lane >> 2, tig = lane & 3;
            int col = ntl * 8 + gid;
            u32 b0h, b0l, b1h, b1l;
            bsplit2(W[2 * tig][col],     W[2 * tig + 1][col], b0h, b0l);
            bsplit2(W[2 * tig + 8][col], W[2 * tig + 9][col], b1h, b1l);
            g_wf[((size_t)ks * 128 + ct * 16 + ntl) * 32 + lane] =
                make_uint4(b0h, b1h, b0l, b1l);
        }
    }
}

// ---------------------------------------------------------------------------
// K_pwf: projection weights -> split-bf16 B fragments.
// ---------------------------------------------------------------------------
__global__ __launch_bounds__(256) void k_pwf(const float* __restrict__ aw) {
    int f = blockIdx.x * 256 + threadIdx.x;     // 16384 frags
    int lane = f & 31, nt = (f >> 5) & 31, ks = f >> 10;
    int gid = lane >> 2, tig = lane & 3;
    const float* src = aw + (size_t)(nt * 8 + gid) * 256 + ks * 16 + 2 * tig;
    u32 b0h, b0l, b1h, b1l;
    bsplit2(src[0], src[1], b0h, b0l);
    bsplit2(src[8], src[9], b1h, b1l);
    g_pf[f] = make_uint4(b0h, b1h, b0l, b1l);
}

// ---------------------------------------------------------------------------
// K_gemm v7: M=128 x N=256, 512 thr (8m x 2n), 3-stage cp.async pipeline.
// At iter ch: issue ch+2, compute ch, wait_group 1 (ch+1 complete) — each
// transfer has a full iteration in flight. smem: 3 x 3072 uint4 = 147456 B.
// ---------------------------------------------------------------------------
__global__ __launch_bounds__(512) void k_gemm(const float* __restrict__ cb,
                                              const float* __restrict__ qb,
                                              float* __restrict__ out) {
    extern __shared__ __align__(16) uint4 SM4[];
    const int tid = threadIdx.x, w = tid >> 5, lane = tid & 31;
    const int gid = lane >> 2, tig = lane & 3;
    const int mpart = w & 7, npart = w >> 3;     // 8 m-parts x 2 n-parts
    const int ptb8 = blockIdx.x;
    const int pt = ptb8 * 8 + mpart;
    const int by = blockIdx.y;

    float c[16][4];
#pragma unroll
    for (int nt = 0; nt < 16; nt++)
#pragma unroll
        for (int r = 0; r < 4; r++) c[nt][r] = 0.f;

    const u32 sb = (u32)__cvta_generic_to_shared(SM4);

    // stage = 3072 uint4: B 2048 + A 1024.
#define ISSUE_CHUNK(chunk, stg)                                                 \
    do {                                                                        \
        int _ks0 = (chunk) * 2;                                                 \
        _Pragma("unroll")                                                       \
        for (int i = 0; i < 4; i++) {                                           \
            int t = tid + i * 512;                                              \
            int ks2 = t >> 10, ntl = (t >> 5) & 31, ln = t & 31;                \
            cp16(sb + ((stg) * 3072 + t) * 16,                                  \
                 g_wf + ((size_t)(_ks0 + ks2) * 128 + by * 32 + ntl) * 32 + ln);\
        }                                                                       \
        _Pragma("unroll")                                                       \
        for (int i = 0; i < 2; i++) {                                           \
            int ta = tid + i * 512;                                             \
            int ks2 = ta >> 9, ptl = (ta >> 6) & 7, hl = (ta >> 5) & 1,         \
                ln = ta & 31;                                                   \
            cp16(sb + ((stg) * 3072 + 2048 + ta) * 16,                          \
                 (hl ? g_xf_lo : g_xf_hi)                                       \
                 + ((size_t)(ptb8 * 8 + ptl) * 72 + _ks0 + ks2) * 32 + ln);     \
        }                                                                       \
        CP_COMMIT();                                                            \
    } while (0)

    ISSUE_CHUNK(0, 0);
    ISSUE_CHUNK(1, 1);
    CP_WAIT1();                 // chunk 0 complete (chunk 1 may be in flight)
    __syncthreads();

    for (int ch = 0; ch < 36; ch++) {
        const int stg = ch % 3;
        if (ch + 2 < 36) ISSUE_CHUNK(ch + 2, (ch + 2) % 3);
#pragma unroll
        for (int ks2 = 0; ks2 < 2; ks2++) {
            uint4 ah = SM4[stg * 3072 + 2048 + ks2 * 512 + mpart * 64 + lane];
            uint4 al = SM4[stg * 3072 + 2048 + ks2 * 512 + mpart * 64 + 32 + lane];
#pragma unroll
            for (int nt = 0; nt < 16; nt++) {
                uint4 bb = SM4[stg * 3072 + ks2 * 1024 + (npart * 16 + nt) * 32 + lane];
                MMA_BF16(c[nt][0], c[nt][1], c[nt][2], c[nt][3],
                         ah.x, ah.y, ah.z, ah.w, bb.x, bb.y);
                MMA_BF16(c[nt][0], c[nt][1], c[nt][2], c[nt][3],
                         ah.x, ah.y, ah.z, ah.w, bb.z, bb.w);
                MMA_BF16(c[nt][0], c[nt][1], c[nt][2], c[nt][3],
                         al.x, al.y, al.z, al.w, bb.x, bb.y);
            }
        }
        if (ch < 35) {
            if (ch + 2 < 36) { CP_WAIT1(); }   // chunk ch+1 complete
            else             { CP_WAIT0(); }   // drain last chunk
        }
        __syncthreads();
    }
#undef ISSUE_CHUNK

    const int r0g = pt * 16 + gid, r1g = r0g + 8;
    const int b = r0g >> 10;
    const int p0 = r0g & 1023, p1 = r1g & 1023;
    if (by == 0) {
#pragma unroll
        for (int nt = 0; nt < 16; nt++) {
            int co = npart * 128 + nt * 8 + 2 * tig;
            float bb0 = cb[co], bb1 = cb[co + 1];
            float* o0 = out + (size_t)(b * 512 + co) * 1024;
            o0[p0] = c[nt][0] + bb0;
            o0[p1] = c[nt][2] + bb0;
            o0 += 1024;
            o0[p0] = c[nt][1] + bb1;
            o0[p1] = c[nt][3] + bb1;
        }
    } else {
        const int seg = by - 1;
        float* base = seg == 0 ? g_q : (seg == 1 ? g_k : g_v);
        const float scale = (seg == 0) ? QSCALE : 1.f;
#pragma unroll
        for (int nt = 0; nt < 16; nt++) {
            int c8 = npart * 128 + nt * 8 + 2 * tig;
            int qc = seg * 256 + c8;
            int h = c8 >> 5, d0 = c8 & 31;
            float bb0 = qb[qc], bb1 = qb[qc + 1];
            float* dst = base + (size_t)((b * 8 + h) * 1024) * 32 + d0;
            *(float2*)(dst + (size_t)p0 * 32) =
                make_float2((c[nt][0] + bb0) * scale, (c[nt][1] + bb1) * scale);
            *(float2*)(dst + (size_t)p1 * 32) =
                make_float2((c[nt][2] + bb0) * scale, (c[nt][3] + bb1) * scale);
        }
    }
}

// ---------------------------------------------------------------------------
// K2: rel-logit tables. float4 LDS (stride-36 rows: conflict-free LDS.128).
// ---------------------------------------------------------------------------
__global__ __launch_bounds__(256) void k_rel(const float* __restrict__ krx,
                                             const float* __restrict__ kry) {
    __shared__ __align__(16) float KX[63 * 36], KY[63 * 36];
    __shared__ __align__(16) float QR[32 * 32], QT[32 * 32];
    const int bh = blockIdx.x, qg = blockIdx.y, tid = threadIdx.x;

    for (int t = tid; t < 63 * 32; t += 256) {
        int m = t >> 5, d = t & 31;
        KX[m * 36 + d] = krx[t];
        KY[m * 36 + d] = kry[t];
    }
    for (int t = tid; t < 1024; t += 256) {
        int il = t >> 5, d = t & 31;
        QR[t] = g_q[(size_t)(bh * 1024 + qg * 32 + il) * 32 + d];
        QT[t] = g_q[(size_t)(bh * 1024 + il * 32 + qg) * 32 + d];
    }
    __syncthreads();

    const int wid = tid >> 5, j = tid & 31;
#pragma unroll
    for (int r = 0; r < 4; r++) {
        int il = r * 8 + wid;
        int m = j - il + 31;
        const float4* qr = (const float4*)(QR + il * 32);
        const float4* qt = (const float4*)(QT + il * 32);
        const float4* kx = (const float4*)(KX + m * 36);
        const float4* ky = (const float4*)(KY + m * 36);
        float ax = 0.f, ay = 0.f;
#pragma unroll
        for (int dd = 0; dd < 8; dd++) {
            float4 a = qr[dd], k = kx[dd];
            ax += a.x * k.x + a.y * k.y + a.z * k.z + a.w * k.w;
            float4 b = qt[dd], k2 = ky[dd];
            ay += b.x * k2.x + b.y * k2.y + b.z * k2.z + b.w * k2.w;
        }
        int i = qg * 32 + il;
        g_rx[(size_t)(bh * 1024 + i) * 32 + j] = ax;
        g_ry[(size_t)(bh * 1024 + i) * 32 + j] = ay;
    }
}

// ---------------------------------------------------------------------------
// K2b: fragment prep — split-bf16 K B-frags (k16) + sigma-permuted tf32 V frags.
// ---------------------------------------------------------------------------
__global__ __launch_bounds__(256) void k_prep() {
    __shared__ float Ksm[128 * 33], Vsm[128 * 33];
    const int bh = blockIdx.x, c = blockIdx.y, tid = threadIdx.x;
    const int j0 = c * 128;

    for (int t = tid; t < 1024; t += 256) {
        int r = t >> 3, f = (t & 7) * 4;
        float4 kv = *(const float4*)&g_k[(size_t)(bh * 1024 + j0 + r) * 32 + f];
        Ksm[r * 33 + f] = kv.x; Ksm[r * 33 + f + 1] = kv.y;
        Ksm[r * 33 + f + 2] = kv.z; Ksm[r * 33 + f + 3] = kv.w;
        float4 vv = *(const float4*)&g_v[(size_t)(bh * 1024 + j0 + r) * 32 + f];
        Vsm[r * 33 + f] = vv.x; Vsm[r * 33 + f + 1] = vv.y;
        Vsm[r * 33 + f + 2] = vv.z; Vsm[r * 33 + f + 3] = vv.w;
    }
    __syncthreads();

    for (int t = tid; t < 1024; t += 256) {
        int lane = t & 31, s = (t >> 5) & 1, ntl = t >> 6;
        int gid = lane >> 2, tig = lane & 3;
        int j = ntl * 8 + gid;
        int k0 = s * 16 + 2 * tig;
        u32 b0h, b0l, b1h, b1l;
        bsplit2(Ksm[j * 33 + k0],     Ksm[j * 33 + k0 + 1], b0h, b0l);
        bsplit2(Ksm[j * 33 + k0 + 8], Ksm[j * 33 + k0 + 9], b1h, b1l);
        g_kbf[(size_t)((bh * 128 + c * 16 + ntl) * 2 + s) * 32 + lane] =
            make_uint4(b0h, b1h, b0l, b1l);
    }
    for (int t = tid; t < 2048; t += 256) {
        int lane = t & 31, dt = (t >> 5) & 3, ktl = t >> 7;
        int gid = lane >> 2, tig = lane & 3;
        u32 b0 = tf32_of(Vsm[(ktl * 8 + 2 * tig)     * 33 + dt * 8 + gid]);
        u32 b1 = tf32_of(Vsm[(ktl * 8 + 2 * tig + 1) * 33 + dt * 8 + gid]);
        g_vf[(size_t)((bh * 128 + c * 16 + ktl) * 4 + dt) * 32 + lane] =
            make_float2(__uint_as_float(b0), __uint_as_float(b1));
    }
}

// ---------------------------------------------------------------------------
// K3: register-flash tensor-core attention, v6 (shuffle-free PV; unchanged).
// ---------------------------------------------------------------------------
__global__ void __launch_bounds__(256, 2) k_attn() {
    __shared__ float RXs[128 * 33], RYs[128 * 33];

    const int bh = blockIdx.x, qt = blockIdx.y;
    const int tid = threadIdx.x, w = tid >> 5, lane = tid & 31;
    const int gid = lane >> 2, tig = lane & 3;
    const int qb = qt * 128;
    const int lq = w * 16;
    const size_t qbase = (size_t)bh * 1024 * 32;

    for (int t = tid; t < 128 * 32; t += 256) {
        int r = t >> 5, cc = t & 31;
        RXs[r * 33 + cc] = g_rx[(size_t)(bh * 1024 + qb + r) * 32 + cc];
        RYs[r * 33 + cc] = g_ry[(size_t)(bh * 1024 + qb + r) * 32 + cc];
    }

    u32 qh[2][4], ql[2][4];
    {
        const float* q0 = g_q + qbase + (size_t)(qb + lq + gid) * 32;
        const float* q1 = q0 + 8 * 32;
#pragma unroll
        for (int s = 0; s < 2; s++) {
            int k0 = s * 16 + 2 * tig;
            bsplit2(q0[k0],     q0[k0 + 1], qh[s][0], ql[s][0]);
            bsplit2(q1[k0],     q1[k0 + 1], qh[s][1], ql[s][1]);
            bsplit2(q0[k0 + 8], q0[k0 + 9], qh[s][2], ql[s][2]);
            bsplit2(q1[k0 + 8], q1[k0 + 9], qh[s][3], ql[s][3]);
        }
    }
    __syncthreads();

    const int lrA = lq + gid, lrB = lrA + 8;

    float rxe[2][4], rxo[2][4];
#pragma unroll
    for (int k = 0; k < 4; k++) {
        rxe[0][k] = RXs[lrA * 33 + 8 * k + 2 * tig];
        rxo[0][k] = RXs[lrA * 33 + 8 * k + 2 * tig + 1];
        rxe[1][k] = RXs[lrB * 33 + 8 * k + 2 * tig];
        rxo[1][k] = RXs[lrB * 33 + 8 * k + 2 * tig + 1];
    }

    float l0 = 0.f, l1 = 0.f;
    float o[4][4];
#pragma unroll
    for (int dt = 0; dt < 4; dt++)
#pragma unroll
        for (int r = 0; r < 4; r++) o[dt][r] = 0.f;

    const uint4*  kf = g_kbf + (size_t)bh * 8192 + lane;
    const float2* vf = g_vf + (size_t)bh * 16384 + lane;

    for (int nt4 = 0; nt4 < 32; nt4++) {
        const float ryA = RYs[lrA * 33 + nt4];
        const float ryB = RYs[lrB * 33 + nt4];

#pragma unroll
        for (int u = 0; u < 4; u++) {
            const int nt = nt4 * 4 + u;
            float dh[4] = {0.f, 0.f, 0.f, 0.f};
            float dx[4] = {0.f, 0.f, 0.f, 0.f};
#pragma unroll
            for (int s = 0; s < 2; s++) {
                uint4 kb = kf[(nt * 2 + s) * 32];
                MMA_BF16(dh[0], dh[1], dh[2], dh[3],
                         qh[s][0], qh[s][1], qh[s][2], qh[s][3], kb.x, kb.y);
                MMA_BF16(dx[0], dx[1], dx[2], dx[3],
                         qh[s][0], qh[s][1], qh[s][2], qh[s][3], kb.z, kb.w);
                MMA_BF16(dx[0], dx[1], dx[2], dx[3],
                         ql[s][0], ql[s][1], ql[s][2], ql[s][3], kb.x, kb.y);
            }
            float p0 = __uint_as_float(tf32_of(__expf(dh[0] + dx[0] + rxe[0][u] + ryA)));
            float p1 = __uint_as_float(tf32_of(__expf(dh[1] + dx[1] + rxo[0][u] + ryA)));
            float p2 = __uint_as_float(tf32_of(__expf(dh[2] + dx[2] + rxe[1][u] + ryB)));
            float p3 = __uint_as_float(tf32_of(__expf(dh[3] + dx[3] + rxo[1][u] + ryB)));
            l0 += p0 + p1;
            l1 += p2 + p3;
            u32 a0 = __float_as_uint(p0);
            u32 a1 = __float_as_uint(p2);
            u32 a2 = __float_as_uint(p1);
            u32 a3 = __float_as_uint(p3);
#pragma unroll
            for (int dt = 0; dt < 4; dt++) {
                float2 vv = vf[(nt * 4 + dt) * 32];
                u32 b0 = __float_as_uint(vv.x), b1 = __float_as_uint(vv.y);
                MMA_TF32(o[dt][0], o[dt][1], o[dt][2], o[dt][3],
                         a0, a1, a2, a3, b0, b1);
            }
        }
    }

    l0 += __shfl_xor_sync(0xffffffffu, l0, 1);
    l0 += __shfl_xor_sync(0xffffffffu, l0, 2);
    l1 += __shfl_xor_sync(0xffffffffu, l1, 1);
    l1 += __shfl_xor_sync(0xffffffffu, l1, 2);
    const float inv0 = 1.0f / l0, inv1 = 1.0f / l1;

    const int b = bh >> 3, h = bh & 7;
    {
        int i = qb + lrA;
        float* dst = g_att + (size_t)(b * 256 + h * 32 + (i >> 5)) * 1024
                   + (i & 31) * 32 + 2 * tig;
#pragma unroll
        for (int dt = 0; dt < 4; dt++)
            *(float2*)(dst + dt * 8) = make_float2(o[dt][0] * inv0, o[dt][1] * inv0);
    }
    {
        int i = qb + lrB;
        float* dst = g_att + (size_t)(b * 256 + h * 32 + (i >> 5)) * 1024
                   + (i & 31) * 32 + 2 * tig;
#pragma unroll
        for (int dt = 0; dt < 4; dt++)
            *(float2*)(dst + dt * 8) = make_float2(o[dt][2] * inv1, o[dt][3] * inv1);
    }
}

// ---------------------------------------------------------------------------
// K4: 1x1 projection as split-bf16 MMA GEMM (unchanged).
// ---------------------------------------------------------------------------
__global__ __launch_bounds__(256) void k_proj(const float* __restrict__ ab,
                                              float* __restrict__ out) {
    __shared__ float As[16][132];
    const int bx = blockIdx.x;
    const int b = bx >> 3, pt = bx & 7;
    const int by = blockIdx.y;
    const int pos0 = pt * 128;
    const int tid = threadIdx.x, w = tid >> 5, lane = tid & 31;
    const int gid = lane >> 2, tig = lane & 3;
    const int wm = w & 3, wn = w >> 2;

    float c[2][4][4];
#pragma unroll
    for (int mt = 0; mt < 2; mt++)
#pragma unroll
        for (int nt = 0; nt < 4; nt++)
#pragma unroll
            for (int r = 0; r < 4; r++) c[mt][nt][r] = 0.f;

    for (int ks = 0; ks < 16; ks++) {
        __syncthreads();
        for (int t = tid; t < 2048; t += 256) {
            int cc = t >> 7, pl = t & 127;
            As[cc][pl] = g_att[(size_t)(b * 256 + ks * 16 + cc) * 1024 + pos0 + pl];
        }
        __syncthreads();

        uint4 kb[4];
#pragma unroll
        for (int nt = 0; nt < 4; nt++)
            kb[nt] = g_pf[(size_t)(ks * 32 + by * 8 + wn * 4 + nt) * 32 + lane];

#pragma unroll
        for (int mt = 0; mt < 2; mt++) {
            int r0 = wm * 32 + mt * 16 + gid, r1 = r0 + 8;
            int k0 = 2 * tig;
            u32 ah[4], al[4];
            bsplit2(As[k0][r0],     As[k0 + 1][r0], ah[0], al[0]);
            bsplit2(As[k0][r1],     As[k0 + 1][r1], ah[1], al[1]);
            bsplit2(As[k0 + 8][r0], As[k0 + 9][r0], ah[2], al[2]);
            bsplit2(As[k0 + 8][r1], As[k0 + 9][r1], ah[3], al[3]);
#pragma unroll
            for (int nt = 0; nt < 4; nt++) {
                MMA_BF16(c[mt][nt][0], c[mt][nt][1], c[mt][nt][2], c[mt][nt][3],
                         ah[0], ah[1], ah[2], ah[3], kb[nt].x, kb[nt].y);
                MMA_BF16(c[mt][nt][0], c[mt][nt][1], c[mt][nt][2], c[mt][nt][3],
                         ah[0], ah[1], ah[2], ah[3], kb[nt].z, kb[nt].w);
                MMA_BF16(c[mt][nt][0], c[mt][nt][1], c[mt][nt][2], c[mt][nt][3],
                         al[0], al[1], al[2], al[3], kb[nt].x, kb[nt].y);
            }
        }
    }

#pragma unroll
    for (int nt = 0; nt < 4; nt++) {
        int co = by * 64 + wn * 32 + nt * 8 + 2 * tig;
        float bb0 = ab[co], bb1 = ab[co + 1];
        float* o0 = out + (size_t)(b * 512 + 256 + co) * 1024 + pos0;
        float* o1 = o0 + 1024;
#pragma unroll
        for (int mt = 0; mt < 2; mt++) {
            int p0 = wm * 32 + mt * 16 + gid, p1 = p0 + 8;
            o0[p0] = c[mt][nt][0] + bb0;
            o1[p0] = c[mt][nt][1] + bb1;
            o0[p1] = c[mt][nt][2] + bb0;
            o1[p1] = c[mt][nt][3] + bb1;
        }
    }
}

// ---------------------------------------------------------------------------
extern "C" void kernel_launch(void* const* d_in, const int* in_sizes, int n_in,
                              void* d_out, int out_size) {
    const float* x   = (const float*)d_in[0];
    const float* cw  = (const float*)d_in[1];
    const float* cb  = (const float*)d_in[2];
    const float* qw  = (const float*)d_in[3];
    const float* qb  = (const float*)d_in[4];
    const float* aw  = (const float*)d_in[5];
    const float* ab  = (const float*)d_in[6];
    const float* krx = (const float*)d_in[7];
    const float* kry = (const float*)d_in[8];
    float* out = (float*)d_out;

    const int gemm_smem = 9216 * 16;   // 147456 B (3 stages)
    static int s_attr_done = 0;
    if (!s_attr_done) {
        cudaFuncSetAttribute(k_gemm, cudaFuncAttributeMaxDynamicSharedMemorySize,
                             gemm_smem);
        s_attr_done = 1;
    }

    k_xf  <<<256, 256>>>(x);
    k_wf  <<<dim3(8, 8), 256>>>(cw, qw);
    k_pwf <<<64, 256>>>(aw);
    k_gemm<<<dim3(32, 4), 512, gemm_smem>>>(cb, qb, out);
    k_rel <<<dim3(32, 32), 256>>>(krx, kry);
    k_prep<<<dim3(32, 8), 256>>>();
    k_attn<<<dim3(32, 8), 256>>>();
    k_proj<<<dim3(32, 4), 256>>>(ab, out);
}

// round 17
// speedup vs baseline: 1.0218x; 1.0218x over previous
#include <cuda_runtime.h>
#include <cuda_bf16.h>

#define QSCALE 0.17677669529663687f   // 32^-0.5

typedef unsigned long long u64;
typedef unsigned int u32;

// ---------------------------------------------------------------------------
// Scratch (static device arrays; no allocation allowed)
// ---------------------------------------------------------------------------
__device__ __align__(16) float g_q  [32 * 1024 * 32];     // [bh][pos][d] (scaled)
__device__ __align__(16) float g_k  [32 * 1024 * 32];
__device__ __align__(16) float g_v  [32 * 1024 * 32];
__device__ __align__(16) float g_rx [32 * 1024 * 32];     // [bh][i][jc]
__device__ __align__(16) float g_ry [32 * 1024 * 32];     // [bh][i][jr]
__device__ __align__(16) float g_att[4 * 256 * 1024];     // scrambled-channel att
__device__ __align__(16) uint4  g_kbf[32 * 128 * 2 * 32]; // split-bf16 K B-frags
__device__ __align__(16) float2 g_vf[32 * 128 * 4 * 32];  // tf32 V frags (row-permuted)
__device__ __align__(16) uint4 g_xf_hi[256 * 72 * 32];    // im2col A frags (bf16 hi)
__device__ __align__(16) uint4 g_xf_lo[256 * 72 * 32];    // im2col A frags (bf16 lo)
__device__ __align__(16) uint4 g_wf   [72 * 128 * 32];    // conv weight B frags
__device__ __align__(16) uint4 g_pf   [16 * 32 * 32];     // proj weight B frags

// ---------------------------------------------------------------------------
// bf16 helpers
// ---------------------------------------------------------------------------
__device__ __forceinline__ u32 bpack(__nv_bfloat16 a, __nv_bfloat16 b) {
    return (u32)__bfloat16_as_ushort(a) | ((u32)__bfloat16_as_ushort(b) << 16);
}
__device__ __forceinline__ void bsplit2(float v0, float v1, u32& hi, u32& lo) {
    __nv_bfloat16 h0 = __float2bfloat16_rn(v0), h1 = __float2bfloat16_rn(v1);
    __nv_bfloat16 l0 = __float2bfloat16_rn(v0 - __bfloat162float(h0));
    __nv_bfloat16 l1 = __float2bfloat16_rn(v1 - __bfloat162float(h1));
    hi = bpack(h0, h1); lo = bpack(l0, l1);
}
#define MMA_BF16(d0,d1,d2,d3,a0,a1,a2,a3,b0,b1)                                \
    asm("mma.sync.aligned.m16n8k16.row.col.f32.bf16.bf16.f32 "                  \
        "{%0,%1,%2,%3},{%4,%5,%6,%7},{%8,%9},{%0,%1,%2,%3};"                    \
        : "+f"(d0), "+f"(d1), "+f"(d2), "+f"(d3)                                \
        : "r"(a0), "r"(a1), "r"(a2), "r"(a3), "r"(b0), "r"(b1))

__device__ __forceinline__ void cp16(u32 saddr, const void* g) {
    asm volatile("cp.async.cg.shared.global [%0], [%1], 16;" :: "r"(saddr), "l"(g));
}
#define CP_COMMIT() asm volatile("cp.async.commit_group;")
#define CP_WAIT0()  asm volatile("cp.async.wait_group 0;")

// ---------------------------------------------------------------------------
// tf32 helpers
// ---------------------------------------------------------------------------
__device__ __forceinline__ u32 tf32_of(float f) {
    u32 r; asm("cvt.rna.tf32.f32 %0,%1;" : "=r"(r) : "f"(f)); return r;
}
#define MMA_TF32(d0,d1,d2,d3,a0,a1,a2,a3,b0,b1)                                \
    asm("mma.sync.aligned.m16n8k8.row.col.f32.tf32.tf32.f32 "                   \
        "{%0,%1,%2,%3},{%4,%5,%6,%7},{%8,%9},{%0,%1,%2,%3};"                    \
        : "+f"(d0), "+f"(d1), "+f"(d2), "+f"(d3)                                \
        : "r"(a0), "r"(a1), "r"(a2), "r"(a3), "r"(b0), "r"(b1))

// ---------------------------------------------------------------------------
// K_xf: im2col -> split-bf16 A fragments in MMA lane order.
// ---------------------------------------------------------------------------
__global__ __launch_bounds__(256) void k_xf(const float* __restrict__ x) {
    __shared__ float Xs[128][3][20];
    const int pt = blockIdx.x, tid = threadIdx.x;
    const int pos0 = pt * 16;
    const int b = pos0 >> 10, y = (pos0 >> 5) & 31, x0 = pos0 & 31;

    for (int t = tid; t < 128 * 54; t += 256) {
        int ci = t / 54, rem = t - ci * 54;
        int ky = rem / 18, cc = rem - ky * 18;
        int gy = y + ky - 1, gx = x0 - 1 + cc;
        float v = 0.f;
        if ((unsigned)gy < 32u && (unsigned)gx < 32u)
            v = x[(size_t)((b * 128 + ci) * 32 + gy) * 32 + gx];
        Xs[ci][ky][cc] = v;
    }
    __syncthreads();

    for (int u = tid; u < 72 * 32; u += 256) {
        int ks = u >> 5, lane = u & 31;
        int gid = lane >> 2, tig = lane & 3;
        int r0 = gid, r1 = gid + 8;
        u32 hi[4], lo[4];
#pragma unroll
        for (int half = 0; half < 2; half++) {
            int k0 = ks * 16 + 2 * tig + half * 8;
            int k1 = k0 + 1;
            int ci0 = k0 / 9, tp0 = k0 - ci0 * 9;
            int ci1 = k1 / 9, tp1 = k1 - ci1 * 9;
            int ky0 = tp0 / 3, kx0 = tp0 - ky0 * 3;
            int ky1 = tp1 / 3, kx1 = tp1 - ky1 * 3;
            float A00 = Xs[ci0][ky0][r0 + kx0];
            float A01 = Xs[ci1][ky1][r0 + kx1];
            float A10 = Xs[ci0][ky0][r1 + kx0];
            float A11 = Xs[ci1][ky1][r1 + kx1];
            bsplit2(A00, A01, hi[half * 2],     lo[half * 2]);
            bsplit2(A10, A11, hi[half * 2 + 1], lo[half * 2 + 1]);
        }
        size_t idx = ((size_t)pt * 72 + ks) * 32 + lane;
        g_xf_hi[idx] = make_uint4(hi[0], hi[1], hi[2], hi[3]);
        g_xf_lo[idx] = make_uint4(lo[0], lo[1], lo[2], lo[3]);
    }
}

// ---------------------------------------------------------------------------
// K_wf: conv weights -> split-bf16 B fragments.
// ---------------------------------------------------------------------------
__global__ __launch_bounds__(256) void k_wf(const float* __restrict__ cw,
                                            const float* __restrict__ qw) {
    __shared__ float W[16][132];
    const int ct = blockIdx.x, ks0 = blockIdx.y * 9, tid = threadIdx.x;
    for (int ks = ks0; ks < ks0 + 9; ks++) {
        __syncthreads();
        for (int t = tid; t < 2048; t += 256) {
            int kl = t & 15, col = t >> 4;
            int co = ct * 128 + col;
            const float* src = (co < 256) ? cw + (size_t)co * 1152
                                          : qw + (size_t)(co - 256) * 1152;
            W[kl][col] = src[ks * 16 + kl];
        }
        __syncthreads();
        for (int u = tid; u < 512; u += 256) {
            int ntl = u >> 5, lane = u & 31, gid = lane >> 2, tig = lane & 3;
            int col = ntl * 8 + gid;
            u32 b0h, b0l, b1h, b1l;
            bsplit2(W[2 * tig][col],     W[2 * tig + 1][col], b0h, b0l);
            bsplit2(W[2 * tig + 8][col], W[2 * tig + 9][col], b1h, b1l);
            g_wf[((size_t)ks * 128 + ct * 16 + ntl) * 32 + lane] =
                make_uint4(b0h, b1h, b0l, b1l);
        }
    }
}

// ---------------------------------------------------------------------------
// K_pwf: projection weights -> split-bf16 B fragments.
// ---------------------------------------------------------------------------
__global__ __launch_bounds__(256) void k_pwf(const float* __restrict__ aw) {
    int f = blockIdx.x * 256 + threadIdx.x;     // 16384 frags
    int lane = f & 31, nt = (f >> 5) & 31, ks = f >> 10;
    int gid = lane >> 2, tig = lane & 3;
    const float* src = aw + (size_t)(nt * 8 + gid) * 256 + ks * 16 + 2 * tig;
    u32 b0h, b0l, b1h, b1l;
    bsplit2(src[0], src[1], b0h, b0l);
    bsplit2(src[8], src[9], b1h, b1l);
    g_pf[f] = make_uint4(b0h, b1h, b0l, b1l);
}

// ---------------------------------------------------------------------------
// K_gemm v6 (round-15 winner): M=128 x N=256, 512 thr (8m x 2n), 2-stage.
// Dynamic smem: 2 x (B 2048 + A 1024) uint4 = 98304 bytes.
// ---------------------------------------------------------------------------
__global__ __launch_bounds__(512) void k_gemm(const float* __restrict__ cb,
                                              const float* __restrict__ qb,
                                              float* __restrict__ out) {
    extern __shared__ __align__(16) uint4 SM4[];
    const int tid = threadIdx.x, w = tid >> 5, lane = tid & 31;
    const int gid = lane >> 2, tig = lane & 3;
    const int mpart = w & 7, npart = w >> 3;
    const int ptb8 = blockIdx.x;
    const int pt = ptb8 * 8 + mpart;
    const int by = blockIdx.y;

    float c[16][4];
#pragma unroll
    for (int nt = 0; nt < 16; nt++)
#pragma unroll
        for (int r = 0; r < 4; r++) c[nt][r] = 0.f;

    const u32 sb = (u32)__cvta_generic_to_shared(SM4);

#define ISSUE_CHUNK(chunk, buf)                                                 \
    do {                                                                        \
        int _ks0 = (chunk) * 2;                                                 \
        _Pragma("unroll")                                                       \
        for (int i = 0; i < 4; i++) {                                           \
            int t = tid + i * 512;                                              \
            int ks2 = t >> 10, ntl = (t >> 5) & 31, ln = t & 31;                \
            cp16(sb + ((buf) * 3072 + t) * 16,                                  \
                 g_wf + ((size_t)(_ks0 + ks2) * 128 + by * 32 + ntl) * 32 + ln);\
        }                                                                       \
        _Pragma("unroll")                                                       \
        for (int i = 0; i < 2; i++) {                                           \
            int ta = tid + i * 512;                                             \
            int ks2 = ta >> 9, ptl = (ta >> 6) & 7, hl = (ta >> 5) & 1,         \
                ln = ta & 31;                                                   \
            cp16(sb + ((buf) * 3072 + 2048 + ta) * 16,                          \
                 (hl ? g_xf_lo : g_xf_hi)                                       \
                 + ((size_t)(ptb8 * 8 + ptl) * 72 + _ks0 + ks2) * 32 + ln);     \
        }                                                                       \
        CP_COMMIT();                                                            \
    } while (0)

    ISSUE_CHUNK(0, 0);
    CP_WAIT0();
    __syncthreads();

    for (int ch = 0; ch < 36; ch++) {
        const int buf = ch & 1;
        if (ch < 35) ISSUE_CHUNK(ch + 1, buf ^ 1);
#pragma unroll
        for (int ks2 = 0; ks2 < 2; ks2++) {
            uint4 ah = SM4[buf * 3072 + 2048 + ks2 * 512 + mpart * 64 + lane];
            uint4 al = SM4[buf * 3072 + 2048 + ks2 * 512 + mpart * 64 + 32 + lane];
#pragma unroll
            for (int nt = 0; nt < 16; nt++) {
                uint4 bb = SM4[buf * 3072 + ks2 * 1024 + (npart * 16 + nt) * 32 + lane];
                MMA_BF16(c[nt][0], c[nt][1], c[nt][2], c[nt][3],
                         ah.x, ah.y, ah.z, ah.w, bb.x, bb.y);
                MMA_BF16(c[nt][0], c[nt][1], c[nt][2], c[nt][3],
                         ah.x, ah.y, ah.z, ah.w, bb.z, bb.w);
                MMA_BF16(c[nt][0], c[nt][1], c[nt][2], c[nt][3],
                         al.x, al.y, al.z, al.w, bb.x, bb.y);
            }
        }
        if (ch < 35) CP_WAIT0();
        __syncthreads();
    }
#undef ISSUE_CHUNK

    const int r0g = pt * 16 + gid, r1g = r0g + 8;
    const int b = r0g >> 10;
    const int p0 = r0g & 1023, p1 = r1g & 1023;
    if (by == 0) {
#pragma unroll
        for (int nt = 0; nt < 16; nt++) {
            int co = npart * 128 + nt * 8 + 2 * tig;
            float bb0 = cb[co], bb1 = cb[co + 1];
            float* o0 = out + (size_t)(b * 512 + co) * 1024;
            o0[p0] = c[nt][0] + bb0;
            o0[p1] = c[nt][2] + bb0;
            o0 += 1024;
            o0[p0] = c[nt][1] + bb1;
            o0[p1] = c[nt][3] + bb1;
        }
    } else {
        const int seg = by - 1;
        float* base = seg == 0 ? g_q : (seg == 1 ? g_k : g_v);
        const float scale = (seg == 0) ? QSCALE : 1.f;
#pragma unroll
        for (int nt = 0; nt < 16; nt++) {
            int c8 = npart * 128 + nt * 8 + 2 * tig;
            int qc = seg * 256 + c8;
            int h = c8 >> 5, d0 = c8 & 31;
            float bb0 = qb[qc], bb1 = qb[qc + 1];
            float* dst = base + (size_t)((b * 8 + h) * 1024) * 32 + d0;
            *(float2*)(dst + (size_t)p0 * 32) =
                make_float2((c[nt][0] + bb0) * scale, (c[nt][1] + bb1) * scale);
            *(float2*)(dst + (size_t)p1 * 32) =
                make_float2((c[nt][2] + bb0) * scale, (c[nt][3] + bb1) * scale);
        }
    }
}

// ---------------------------------------------------------------------------
// K2: rel-logit tables. float4 LDS (stride-36 rows: conflict-free LDS.128).
// ---------------------------------------------------------------------------
__global__ __launch_bounds__(256) void k_rel(const float* __restrict__ krx,
                                             const float* __restrict__ kry) {
    __shared__ __align__(16) float KX[63 * 36], KY[63 * 36];
    __shared__ __align__(16) float QR[32 * 32], QT[32 * 32];
    const int bh = blockIdx.x, qg = blockIdx.y, tid = threadIdx.x;

    for (int t = tid; t < 63 * 32; t += 256) {
        int m = t >> 5, d = t & 31;
        KX[m * 36 + d] = krx[t];
        KY[m * 36 + d] = kry[t];
    }
    for (int t = tid; t < 1024; t += 256) {
        int il = t >> 5, d = t & 31;
        QR[t] = g_q[(size_t)(bh * 1024 + qg * 32 + il) * 32 + d];
        QT[t] = g_q[(size_t)(bh * 1024 + il * 32 + qg) * 32 + d];
    }
    __syncthreads();

    const int wid = tid >> 5, j = tid & 31;
#pragma unroll
    for (int r = 0; r < 4; r++) {
        int il = r * 8 + wid;
        int m = j - il + 31;
        const float4* qr = (const float4*)(QR + il * 32);
        const float4* qt = (const float4*)(QT + il * 32);
        const float4* kx = (const float4*)(KX + m * 36);
        const float4* ky = (const float4*)(KY + m * 36);
        float ax = 0.f, ay = 0.f;
#pragma unroll
        for (int dd = 0; dd < 8; dd++) {
            float4 a = qr[dd], k = kx[dd];
            ax += a.x * k.x + a.y * k.y + a.z * k.z + a.w * k.w;
            float4 b = qt[dd], k2 = ky[dd];
            ay += b.x * k2.x + b.y * k2.y + b.z * k2.z + b.w * k2.w;
        }
        int i = qg * 32 + il;
        g_rx[(size_t)(bh * 1024 + i) * 32 + j] = ax;
        g_ry[(size_t)(bh * 1024 + i) * 32 + j] = ay;
    }
}

// ---------------------------------------------------------------------------
// K2b: fragment prep — split-bf16 K B-frags (k16) + sigma-permuted tf32 V frags.
// ---------------------------------------------------------------------------
__global__ __launch_bounds__(256) void k_prep() {
    __shared__ float Ksm[128 * 33], Vsm[128 * 33];
    const int bh = blockIdx.x, c = blockIdx.y, tid = threadIdx.x;
    const int j0 = c * 128;

    for (int t = tid; t < 1024; t += 256) {
        int r = t >> 3, f = (t & 7) * 4;
        float4 kv = *(const float4*)&g_k[(size_t)(bh * 1024 + j0 + r) * 32 + f];
        Ksm[r * 33 + f] = kv.x; Ksm[r * 33 + f + 1] = kv.y;
        Ksm[r * 33 + f + 2] = kv.z; Ksm[r * 33 + f + 3] = kv.w;
        float4 vv = *(const float4*)&g_v[(size_t)(bh * 1024 + j0 + r) * 32 + f];
        Vsm[r * 33 + f] = vv.x; Vsm[r * 33 + f + 1] = vv.y;
        Vsm[r * 33 + f + 2] = vv.z; Vsm[r * 33 + f + 3] = vv.w;
    }
    __syncthreads();

    for (int t = tid; t < 1024; t += 256) {
        int lane = t & 31, s = (t >> 5) & 1, ntl = t >> 6;
        int gid = lane >> 2, tig = lane & 3;
        int j = ntl * 8 + gid;
        int k0 = s * 16 + 2 * tig;
        u32 b0h, b0l, b1h, b1l;
        bsplit2(Ksm[j * 33 + k0],     Ksm[j * 33 + k0 + 1], b0h, b0l);
        bsplit2(Ksm[j * 33 + k0 + 8], Ksm[j * 33 + k0 + 9], b1h, b1l);
        g_kbf[(size_t)((bh * 128 + c * 16 + ntl) * 2 + s) * 32 + lane] =
            make_uint4(b0h, b1h, b0l, b1l);
    }
    for (int t = tid; t < 2048; t += 256) {
        int lane = t & 31, dt = (t >> 5) & 3, ktl = t >> 7;
        int gid = lane >> 2, tig = lane & 3;
        u32 b0 = tf32_of(Vsm[(ktl * 8 + 2 * tig)     * 33 + dt * 8 + gid]);
        u32 b1 = tf32_of(Vsm[(ktl * 8 + 2 * tig + 1) * 33 + dt * 8 + gid]);
        g_vf[(size_t)((bh * 128 + c * 16 + ktl) * 4 + dt) * 32 + lane] =
            make_float2(__uint_as_float(b0), __uint_as_float(b1));
    }
}

// ---------------------------------------------------------------------------
// K3: attention v7 — K/V fragments double-buffer staged via cp.async.
// Chunk = 16 key-tiles: K 16KB + V 16KB (contiguous in g_kbf/g_vf).
// Dynamic smem: Kc 2x16KB | Vc 2x16KB | RX 4224f | RY 4224f = 99328 B.
// ---------------------------------------------------------------------------
__global__ void __launch_bounds__(256, 2) k_attn() {
    extern __shared__ __align__(16) char ASM[];
    uint4*  Kc  = (uint4*)ASM;                        // [2][1024]
    float2* Vc  = (float2*)(ASM + 32768);             // [2][2048]
    float*  RXs = (float*)(ASM + 65536);              // [128*33]
    float*  RYs = RXs + 128 * 33;

    const int bh = blockIdx.x, qt = blockIdx.y;
    const int tid = threadIdx.x, w = tid >> 5, lane = tid & 31;
    const int gid = lane >> 2, tig = lane & 3;
    const int qb = qt * 128;
    const int lq = w * 16;
    const size_t qbase = (size_t)bh * 1024 * 32;

    const u32 sbK = (u32)__cvta_generic_to_shared(Kc);
    const u32 sbV = (u32)__cvta_generic_to_shared(Vc);
    const uint4* ksrc = g_kbf + (size_t)bh * 8192;
    const uint4* vsrc = (const uint4*)(g_vf + (size_t)bh * 16384);

    // stage chunk = 1024 uint4 K + 1024 uint4 V, 8 cp16/thread
#define ATTN_ISSUE(ck, buf)                                                     \
    do {                                                                        \
        _Pragma("unroll")                                                       \
        for (int i = 0; i < 4; i++) {                                           \
            int t = tid + i * 256;                                              \
            cp16(sbK + ((buf) * 1024 + t) * 16, ksrc + (ck) * 1024 + t);        \
            cp16(sbV + ((buf) * 1024 + t) * 16, vsrc + (ck) * 1024 + t);        \
        }                                                                       \
        CP_COMMIT();                                                            \
    } while (0)

    for (int t = tid; t < 128 * 32; t += 256) {
        int r = t >> 5, cc = t & 31;
        RXs[r * 33 + cc] = g_rx[(size_t)(bh * 1024 + qb + r) * 32 + cc];
        RYs[r * 33 + cc] = g_ry[(size_t)(bh * 1024 + qb + r) * 32 + cc];
    }

    ATTN_ISSUE(0, 0);

    u32 qh[2][4], ql[2][4];
    {
        const float* q0 = g_q + qbase + (size_t)(qb + lq + gid) * 32;
        const float* q1 = q0 + 8 * 32;
#pragma unroll
        for (int s = 0; s < 2; s++) {
            int k0 = s * 16 + 2 * tig;
            bsplit2(q0[k0],     q0[k0 + 1], qh[s][0], ql[s][0]);
            bsplit2(q1[k0],     q1[k0 + 1], qh[s][1], ql[s][1]);
            bsplit2(q0[k0 + 8], q0[k0 + 9], qh[s][2], ql[s][2]);
            bsplit2(q1[k0 + 8], q1[k0 + 9], qh[s][3], ql[s][3]);
        }
    }
    CP_WAIT0();
    __syncthreads();

    const int lrA = lq + gid, lrB = lrA + 8;

    float rxe[2][4], rxo[2][4];
#pragma unroll
    for (int k = 0; k < 4; k++) {
        rxe[0][k] = RXs[lrA * 33 + 8 * k + 2 * tig];
        rxo[0][k] = RXs[lrA * 33 + 8 * k + 2 * tig + 1];
        rxe[1][k] = RXs[lrB * 33 + 8 * k + 2 * tig];
        rxo[1][k] = RXs[lrB * 33 + 8 * k + 2 * tig + 1];
    }

    float l0 = 0.f, l1 = 0.f;
    float o[4][4];
#pragma unroll
    for (int dt = 0; dt < 4; dt++)
#pragma unroll
        for (int r = 0; r < 4; r++) o[dt][r] = 0.f;

    for (int ck = 0; ck < 8; ck++) {
        const int buf = ck & 1;
        if (ck < 7) ATTN_ISSUE(ck + 1, buf ^ 1);

#pragma unroll
        for (int nt4l = 0; nt4l < 4; nt4l++) {
            const int nt4 = ck * 4 + nt4l;
            const float ryA = RYs[lrA * 33 + nt4];
            const float ryB = RYs[lrB * 33 + nt4];
#pragma unroll
            for (int u = 0; u < 4; u++) {
                const int ntl = nt4l * 4 + u;
                float dh[4] = {0.f, 0.f, 0.f, 0.f};
                float dx[4] = {0.f, 0.f, 0.f, 0.f};
#pragma unroll
                for (int s = 0; s < 2; s++) {
                    uint4 kb = Kc[buf * 1024 + (ntl * 2 + s) * 32 + lane];
                    MMA_BF16(dh[0], dh[1], dh[2], dh[3],
                             qh[s][0], qh[s][1], qh[s][2], qh[s][3], kb.x, kb.y);
                    MMA_BF16(dx[0], dx[1], dx[2], dx[3],
                             qh[s][0], qh[s][1], qh[s][2], qh[s][3], kb.z, kb.w);
                    MMA_BF16(dx[0], dx[1], dx[2], dx[3],
                             ql[s][0], ql[s][1], ql[s][2], ql[s][3], kb.x, kb.y);
                }
                float p0 = __uint_as_float(tf32_of(__expf(dh[0] + dx[0] + rxe[0][u] + ryA)));
                float p1 = __uint_as_float(tf32_of(__expf(dh[1] + dx[1] + rxo[0][u] + ryA)));
                float p2 = __uint_as_float(tf32_of(__expf(dh[2] + dx[2] + rxe[1][u] + ryB)));
                float p3 = __uint_as_float(tf32_of(__expf(dh[3] + dx[3] + rxo[1][u] + ryB)));
                l0 += p0 + p1;
                l1 += p2 + p3;
                u32 a0 = __float_as_uint(p0);
                u32 a1 = __float_as_uint(p2);
                u32 a2 = __float_as_uint(p1);
                u32 a3 = __float_as_uint(p3);
#pragma unroll
                for (int dt = 0; dt < 4; dt++) {
                    float2 vv = Vc[buf * 2048 + (ntl * 4 + dt) * 32 + lane];
                    u32 b0 = __float_as_uint(vv.x), b1 = __float_as_uint(vv.y);
                    MMA_TF32(o[dt][0], o[dt][1], o[dt][2], o[dt][3],
                             a0, a1, a2, a3, b0, b1);
                }
            }
        }
        if (ck < 7) CP_WAIT0();
        __syncthreads();
    }
#undef ATTN_ISSUE

    l0 += __shfl_xor_sync(0xffffffffu, l0, 1);
    l0 += __shfl_xor_sync(0xffffffffu, l0, 2);
    l1 += __shfl_xor_sync(0xffffffffu, l1, 1);
    l1 += __shfl_xor_sync(0xffffffffu, l1, 2);
    const float inv0 = 1.0f / l0, inv1 = 1.0f / l1;

    const int b = bh >> 3, h = bh & 7;
    {
        int i = qb + lrA;
        float* dst = g_att + (size_t)(b * 256 + h * 32 + (i >> 5)) * 1024
                   + (i & 31) * 32 + 2 * tig;
#pragma unroll
        for (int dt = 0; dt < 4; dt++)
            *(float2*)(dst + dt * 8) = make_float2(o[dt][0] * inv0, o[dt][1] * inv0);
    }
    {
        int i = qb + lrB;
        float* dst = g_att + (size_t)(b * 256 + h * 32 + (i >> 5)) * 1024
                   + (i & 31) * 32 + 2 * tig;
#pragma unroll
        for (int dt = 0; dt < 4; dt++)
            *(float2*)(dst + dt * 8) = make_float2(o[dt][2] * inv1, o[dt][3] * inv1);
    }
}

// ---------------------------------------------------------------------------
// K4: 1x1 projection as split-bf16 MMA GEMM (unchanged).
// ---------------------------------------------------------------------------
__global__ __launch_bounds__(256) void k_proj(const float* __restrict__ ab,
                                              float* __restrict__ out) {
    __shared__ float As[16][132];
    const int bx = blockIdx.x;
    const int b = bx >> 3, pt = bx & 7;
    const int by = blockIdx.y;
    const int pos0 = pt * 128;
    const int tid = threadIdx.x, w = tid >> 5, lane = tid & 31;
    const int gid = lane >> 2, tig = lane & 3;
    const int wm = w & 3, wn = w >> 2;

    float c[2][4][4];
#pragma unroll
    for (int mt = 0; mt < 2; mt++)
#pragma unroll
        for (int nt = 0; nt < 4; nt++)
#pragma unroll
            for (int r = 0; r < 4; r++) c[mt][nt][r] = 0.f;

    for (int ks = 0; ks < 16; ks++) {
        __syncthreads();
        for (int t = tid; t < 2048; t += 256) {
            int cc = t >> 7, pl = t & 127;
            As[cc][pl] = g_att[(size_t)(b * 256 + ks * 16 + cc) * 1024 + pos0 + pl];
        }
        __syncthreads();

        uint4 kb[4];
#pragma unroll
        for (int nt = 0; nt < 4; nt++)
            kb[nt] = g_pf[(size_t)(ks * 32 + by * 8 + wn * 4 + nt) * 32 + lane];

#pragma unroll
        for (int mt = 0; mt < 2; mt++) {
            int r0 = wm * 32 + mt * 16 + gid, r1 = r0 + 8;
            int k0 = 2 * tig;
            u32 ah[4], al[4];
            bsplit2(As[k0][r0],     As[k0 + 1][r0], ah[0], al[0]);
            bsplit2(As[k0][r1],     As[k0 + 1][r1], ah[1], al[1]);
            bsplit2(As[k0 + 8][r0], As[k0 + 9][r0], ah[2], al[2]);
            bsplit2(As[k0 + 8][r1], As[k0 + 9][r1], ah[3], al[3]);
#pragma unroll
            for (int nt = 0; nt < 4; nt++) {
                MMA_BF16(c[mt][nt][0], c[mt][nt][1], c[mt][nt][2], c[mt][nt][3],
                         ah[0], ah[1], ah[2], ah[3], kb[nt].x, kb[nt].y);
                MMA_BF16(c[mt][nt][0], c[mt][nt][1], c[mt][nt][2], c[mt][nt][3],
                         ah[0], ah[1], ah[2], ah[3], kb[nt].z, kb[nt].w);
                MMA_BF16(c[mt][nt][0], c[mt][nt][1], c[mt][nt][2], c[mt][nt][3],
                         al[0], al[1], al[2], al[3], kb[nt].x, kb[nt].y);
            }
        }
    }

#pragma unroll
    for (int nt = 0; nt < 4; nt++) {
        int co = by * 64 + wn * 32 + nt * 8 + 2 * tig;
        float bb0 = ab[co], bb1 = ab[co + 1];
        float* o0 = out + (size_t)(b * 512 + 256 + co) * 1024 + pos0;
        float* o1 = o0 + 1024;
#pragma unroll
        for (int mt = 0; mt < 2; mt++) {
            int p0 = wm * 32 + mt * 16 + gid, p1 = p0 + 8;
            o0[p0] = c[mt][nt][0] + bb0;
            o1[p0] = c[mt][nt][1] + bb1;
            o0[p1] = c[mt][nt][2] + bb0;
            o1[p1] = c[mt][nt][3] + bb1;
        }
    }
}

// ---------------------------------------------------------------------------
extern "C" void kernel_launch(void* const* d_in, const int* in_sizes, int n_in,
                              void* d_out, int out_size) {
    const float* x   = (const float*)d_in[0];
    const float* cw  = (const float*)d_in[1];
    const float* cb  = (const float*)d_in[2];
    const float* qw  = (const float*)d_in[3];
    const float* qb  = (const float*)d_in[4];
    const float* aw  = (const float*)d_in[5];
    const float* ab  = (const float*)d_in[6];
    const float* krx = (const float*)d_in[7];
    const float* kry = (const float*)d_in[8];
    float* out = (float*)d_out;

    const int gemm_smem = 6144 * 16;   // 98304 B
    const int attn_smem = 65536 + 2 * 128 * 33 * 4;   // 99328 B
    static int s_attr_done = 0;
    if (!s_attr_done) {
        cudaFuncSetAttribute(k_gemm, cudaFuncAttributeMaxDynamicSharedMemorySize,
                             gemm_smem);
        cudaFuncSetAttribute(k_attn, cudaFuncAttributeMaxDynamicSharedMemorySize,
                             attn_smem);
        s_attr_done = 1;
    }

    k_xf  <<<256, 256>>>(x);
    k_wf  <<<dim3(8, 8), 256>>>(cw, qw);
    k_pwf <<<64, 256>>>(aw);
    k_gemm<<<dim3(32, 4), 512, gemm_smem>>>(cb, qb, out);
    k_rel <<<dim3(32, 32), 256>>>(krx, kry);
    k_prep<<<dim3(32, 8), 256>>>();
    k_attn<<<dim3(32, 8), 256, attn_smem>>>();
    k_proj<<<dim3(32, 4), 256>>>(ab, out);
}